// round 4
// baseline (speedup 1.0000x reference)
#include <cuda_runtime.h>

#define Nn 384
#define Dm 256
#define MARGIN 0.2f
#define ANCH 4
#define NBLK (Nn / ANCH)   // 96
#define NTHR 768
#define NWARP 24
#define JB 4

__device__ float    g_psum[NBLK];
__device__ int      g_pcnt[NBLK];
__device__ unsigned g_flag;      // zero-init; last block resets to 0 each run

__global__ void __launch_bounds__(NTHR, 1)
k_fused(const float* __restrict__ e, const int* __restrict__ lab,
        float* __restrict__ out) {
    __shared__ float4 ea4[ANCH * 64];    // raw anchor rows (float4 view)
    __shared__ float  Drow[ANCH][Nn];    // raw dots -> distances (in place)
    __shared__ float  sssq[Nn];          // raw squared norms per j
    __shared__ int    slab[Nn];
    __shared__ float  pd2[2][Nn];        // compacted positives, one buf per half
    __shared__ int    wcnt2[2][12];
    __shared__ float  rsum[NWARP];
    __shared__ int    rcnt[NWARP];
    __shared__ int    s_last;

    const int t = threadIdx.x, w = t >> 5, lane = t & 31;
    const int a0 = blockIdx.x * ANCH;

    if (t < Nn) slab[t] = lab[t];
    {
        const float4* src = (const float4*)(e + a0 * Dm);
        if (t < ANCH * 64) ea4[t] = src[t];
    }
    __syncthreads();

    // ---- Phase 2: 8 lanes per j, 4 j's per warp iteration, 24 warps ----
    const int jj = lane >> 3;            // which j within the group of 4
    const int kk = lane & 7;             // which k-slice (8 float4 per lane)

    for (int jb = w * JB; jb < Nn; jb += NWARP * JB) {
        const int j = jb + jj;
        const float4* __restrict__ row = (const float4*)(e + j * Dm);
        float c0 = 0.f, c1 = 0.f, c2 = 0.f, c3 = 0.f, q = 0.f;
        #pragma unroll
        for (int h = 0; h < 2; h++) {
            float4 v[4];
            #pragma unroll
            for (int u = 0; u < 4; u++) v[u] = row[kk + 8 * (4 * h + u)];
            #pragma unroll
            for (int u = 0; u < 4; u++) {
                const int f = kk + 8 * (4 * h + u);
                float4 b0 = ea4[0 * 64 + f];
                float4 b1 = ea4[1 * 64 + f];
                float4 b2 = ea4[2 * 64 + f];
                float4 b3 = ea4[3 * 64 + f];
                q  = fmaf(v[u].x, v[u].x, q);  q  = fmaf(v[u].y, v[u].y, q);
                q  = fmaf(v[u].z, v[u].z, q);  q  = fmaf(v[u].w, v[u].w, q);
                c0 = fmaf(b0.x, v[u].x, c0); c0 = fmaf(b0.y, v[u].y, c0);
                c0 = fmaf(b0.z, v[u].z, c0); c0 = fmaf(b0.w, v[u].w, c0);
                c1 = fmaf(b1.x, v[u].x, c1); c1 = fmaf(b1.y, v[u].y, c1);
                c1 = fmaf(b1.z, v[u].z, c1); c1 = fmaf(b1.w, v[u].w, c1);
                c2 = fmaf(b2.x, v[u].x, c2); c2 = fmaf(b2.y, v[u].y, c2);
                c2 = fmaf(b2.z, v[u].z, c2); c2 = fmaf(b2.w, v[u].w, c2);
                c3 = fmaf(b3.x, v[u].x, c3); c3 = fmaf(b3.y, v[u].y, c3);
                c3 = fmaf(b3.z, v[u].z, c3); c3 = fmaf(b3.w, v[u].w, c3);
            }
        }
        // reduce within 8-lane groups: 3 butterfly steps, 4 j's at once
        #pragma unroll
        for (int o = 1; o < 8; o <<= 1) {
            q  += __shfl_xor_sync(0xffffffffu, q,  o);
            c0 += __shfl_xor_sync(0xffffffffu, c0, o);
            c1 += __shfl_xor_sync(0xffffffffu, c1, o);
            c2 += __shfl_xor_sync(0xffffffffu, c2, o);
            c3 += __shfl_xor_sync(0xffffffffu, c3, o);
        }
        if (kk == 0) {
            sssq[j]    = q;
            Drow[0][j] = c0;
            Drow[1][j] = c1;
            Drow[2][j] = c2;
            Drow[3][j] = c3;
        }
    }
    __syncthreads();

    // ---- Parallel epilogue: raw dot -> distance, threads 0..383 ----
    if (t < Nn) {
        float sj = rsqrtf(fmaxf(sssq[t], 1e-24f));
        #pragma unroll
        for (int aa = 0; aa < ANCH; aa++) {
            float sa = rsqrtf(fmaxf(sssq[a0 + aa], 1e-24f));
            float d2 = 2.0f - 2.0f * Drow[aa][t] * sa * sj;
            d2 = fmaxf(d2, 0.0f);
            Drow[aa][t] = (d2 > 0.0f) ? sqrtf(d2) : 0.0f;
        }
    }
    __syncthreads();

    // ---- Phase 3+4: halves handle 2 anchors each ----
    const int half = t >= Nn ? 1 : 0;
    const int tt   = t - half * Nn;      // 0..383 within half
    const int wh   = tt >> 5;            // warp index within half (0..11)

    float lsum = 0.0f;
    int   lcnt = 0;
    #pragma unroll
    for (int aa2 = 0; aa2 < 2; aa2++) {
        const int aa = half * 2 + aa2;
        const int a  = a0 + aa;
        const int la = slab[a];
        bool isp = (slab[tt] == la) && (tt != a);
        unsigned m = __ballot_sync(0xffffffffu, isp);
        if (lane == 0) wcnt2[half][wh] = __popc(m);
        __syncthreads();
        int off = 0, npos = 0;
        #pragma unroll
        for (int i = 0; i < 12; i++) {
            int c = wcnt2[half][i];
            if (i < wh) off += c;
            npos += c;
        }
        if (isp) pd2[half][off + __popc(m & ((1u << lane) - 1u))] = Drow[aa][tt];
        __syncthreads();

        if (slab[tt] != la) {
            float dn = Drow[aa][tt];
            for (int i = 0; i < npos; i++) {
                float tm = dn - pd2[half][i];
                // semihard & loss>0  <=>  0 < tm < MARGIN (tm==MARGIN adds 0)
                if (tm > 0.0f && tm < MARGIN) { lsum += (MARGIN - tm); lcnt++; }
            }
        }
        __syncthreads();
    }

    // ---- Block reduction (fixed order, deterministic) ----
    #pragma unroll
    for (int o = 16; o > 0; o >>= 1) {
        lsum += __shfl_xor_sync(0xffffffffu, lsum, o);
        lcnt += __shfl_xor_sync(0xffffffffu, lcnt, o);
    }
    if (lane == 0) { rsum[w] = lsum; rcnt[w] = lcnt; }
    __syncthreads();
    if (t == 0) {
        float s = 0.0f; int c = 0;
        #pragma unroll
        for (int i = 0; i < NWARP; i++) { s += rsum[i]; c += rcnt[i]; }
        g_psum[blockIdx.x] = s;
        g_pcnt[blockIdx.x] = c;
        __threadfence();
        unsigned old = atomicAdd(&g_flag, 1u);
        s_last = (old == NBLK - 1) ? 1 : 0;
    }
    __syncthreads();

    // ---- Last block folds the 96 partials (deterministic order) ----
    if (s_last) {
        float s2 = (t < NBLK) ? g_psum[t] : 0.0f;
        int   c2 = (t < NBLK) ? g_pcnt[t] : 0;
        #pragma unroll
        for (int o = 16; o > 0; o >>= 1) {
            s2 += __shfl_xor_sync(0xffffffffu, s2, o);
            c2 += __shfl_xor_sync(0xffffffffu, c2, o);
        }
        if (lane == 0 && w < 3) { rsum[w] = s2; rcnt[w] = c2; }
        __syncthreads();
        if (t == 0) {
            float ts = rsum[0] + rsum[1] + rsum[2];
            int   tc = rcnt[0] + rcnt[1] + rcnt[2];
            out[0] = (tc > 0) ? (ts / (float)tc) : 0.0f;
            g_flag = 0;   // reset for next graph replay
        }
    }
}

extern "C" void kernel_launch(void* const* d_in, const int* in_sizes, int n_in,
                              void* d_out, int out_size) {
    const float* e   = (const float*)d_in[0];
    const int*   lab = (const int*)d_in[1];
    k_fused<<<NBLK, NTHR>>>(e, lab, (float*)d_out);
}

// round 5
// speedup vs baseline: 1.8448x; 1.8448x over previous
#include <cuda_runtime.h>

#define Nn 384
#define Dm 256
#define MARGIN 0.2f
#define ANCH 3
#define NBLK (Nn / ANCH)   // 128
#define NTHR 384
#define NWARP 12
#define JB 4

__device__ float    g_psum[NBLK];
__device__ int      g_pcnt[NBLK];
__device__ unsigned g_flag;      // zero-init; last block resets to 0 each run

__global__ void __launch_bounds__(NTHR, 1)
k_fused(const float* __restrict__ e, const int* __restrict__ lab,
        float* __restrict__ out) {
    __shared__ float4 ea4[ANCH * 64];    // raw anchor rows (float4 view)
    __shared__ float  Drow[ANCH][Nn];    // raw dots -> distances (in place)
    __shared__ float  sssq[Nn];          // raw squared norms per j
    __shared__ int    slab[Nn];
    __shared__ float  pd[Nn];            // compacted positive distances
    __shared__ int    wcnt[NWARP];
    __shared__ float  rsum[NWARP];
    __shared__ int    rcnt[NWARP];
    __shared__ int    s_last;

    const int t = threadIdx.x, w = t >> 5, lane = t & 31;
    const int a0 = blockIdx.x * ANCH;

    if (t < Nn) slab[t] = lab[t];
    {
        const float4* src = (const float4*)(e + a0 * Dm);
        if (t < ANCH * 64) ea4[t] = src[t];
    }
    __syncthreads();

    // ---- Phase 2: 8 lanes per j, 4 j's per warp, software-pipelined LDG ----
    const int jj = lane >> 3;            // which j within the group of 4
    const int kk = lane & 7;             // which k-slice (8 float4 per lane)

    float4 v[8];
    {
        const float4* __restrict__ row = (const float4*)(e + (w * JB + jj) * Dm);
        #pragma unroll
        for (int c = 0; c < 8; c++) v[c] = row[kk + 8 * c];
    }

    for (int jb = w * JB; jb < Nn; jb += NWARP * JB) {
        // prefetch next tile (wraps to row block 0 harmlessly on last iter)
        const int jbn = (jb + NWARP * JB < Nn) ? (jb + NWARP * JB) : 0;
        const float4* __restrict__ rown = (const float4*)(e + (jbn + jj) * Dm);
        float4 nv[8];
        #pragma unroll
        for (int c = 0; c < 8; c++) nv[c] = rown[kk + 8 * c];

        float c0 = 0.f, c1 = 0.f, c2 = 0.f, q = 0.f;
        #pragma unroll
        for (int c = 0; c < 8; c++) {
            const int f = kk + 8 * c;
            float4 b0 = ea4[0 * 64 + f];
            float4 b1 = ea4[1 * 64 + f];
            float4 b2 = ea4[2 * 64 + f];
            q  = fmaf(v[c].x, v[c].x, q);  q  = fmaf(v[c].y, v[c].y, q);
            q  = fmaf(v[c].z, v[c].z, q);  q  = fmaf(v[c].w, v[c].w, q);
            c0 = fmaf(b0.x, v[c].x, c0); c0 = fmaf(b0.y, v[c].y, c0);
            c0 = fmaf(b0.z, v[c].z, c0); c0 = fmaf(b0.w, v[c].w, c0);
            c1 = fmaf(b1.x, v[c].x, c1); c1 = fmaf(b1.y, v[c].y, c1);
            c1 = fmaf(b1.z, v[c].z, c1); c1 = fmaf(b1.w, v[c].w, c1);
            c2 = fmaf(b2.x, v[c].x, c2); c2 = fmaf(b2.y, v[c].y, c2);
            c2 = fmaf(b2.z, v[c].z, c2); c2 = fmaf(b2.w, v[c].w, c2);
        }
        // reduce within 8-lane groups: 3 butterfly steps, 4 j's at once
        #pragma unroll
        for (int o = 1; o < 8; o <<= 1) {
            q  += __shfl_xor_sync(0xffffffffu, q,  o);
            c0 += __shfl_xor_sync(0xffffffffu, c0, o);
            c1 += __shfl_xor_sync(0xffffffffu, c1, o);
            c2 += __shfl_xor_sync(0xffffffffu, c2, o);
        }
        if (kk == 0) {
            const int j = jb + jj;
            sssq[j]    = q;
            Drow[0][j] = c0;
            Drow[1][j] = c1;
            Drow[2][j] = c2;
        }
        #pragma unroll
        for (int c = 0; c < 8; c++) v[c] = nv[c];
    }
    __syncthreads();

    // ---- Parallel epilogue: raw dot -> distance, thread t = column j ----
    {
        float sj = rsqrtf(fmaxf(sssq[t], 1e-24f));
        #pragma unroll
        for (int aa = 0; aa < ANCH; aa++) {
            float sa = rsqrtf(fmaxf(sssq[a0 + aa], 1e-24f));
            float d2 = 2.0f - 2.0f * Drow[aa][t] * sa * sj;
            d2 = fmaxf(d2, 0.0f);
            Drow[aa][t] = (d2 > 0.0f) ? sqrtf(d2) : 0.0f;
        }
    }
    __syncthreads();

    // ---- Phase 3+4: per anchor, ballot-compaction of positives + negative scan ----
    float lsum = 0.0f;
    int   lcnt = 0;
    #pragma unroll
    for (int aa = 0; aa < ANCH; aa++) {
        const int a  = a0 + aa;
        const int la = slab[a];
        bool isp = (slab[t] == la) && (t != a);
        unsigned m = __ballot_sync(0xffffffffu, isp);
        if (lane == 0) wcnt[w] = __popc(m);
        __syncthreads();
        int off = 0, npos = 0;
        #pragma unroll
        for (int i = 0; i < NWARP; i++) {
            int c = wcnt[i];
            if (i < w) off += c;
            npos += c;
        }
        if (isp) pd[off + __popc(m & ((1u << lane) - 1u))] = Drow[aa][t];
        __syncthreads();

        if (slab[t] != la) {
            float dn = Drow[aa][t];
            for (int i = 0; i < npos; i++) {
                float tm = dn - pd[i];
                // semihard & loss>0  <=>  0 < tm < MARGIN (tm==MARGIN adds 0)
                if (tm > 0.0f && tm < MARGIN) { lsum += (MARGIN - tm); lcnt++; }
            }
        }
        __syncthreads();
    }

    // ---- Block reduction (fixed order, deterministic) ----
    #pragma unroll
    for (int o = 16; o > 0; o >>= 1) {
        lsum += __shfl_xor_sync(0xffffffffu, lsum, o);
        lcnt += __shfl_xor_sync(0xffffffffu, lcnt, o);
    }
    if (lane == 0) { rsum[w] = lsum; rcnt[w] = lcnt; }
    __syncthreads();
    if (t == 0) {
        float s = 0.0f; int c = 0;
        #pragma unroll
        for (int i = 0; i < NWARP; i++) { s += rsum[i]; c += rcnt[i]; }
        g_psum[blockIdx.x] = s;
        g_pcnt[blockIdx.x] = c;
        __threadfence();
        unsigned old = atomicAdd(&g_flag, 1u);
        s_last = (old == NBLK - 1) ? 1 : 0;
    }
    __syncthreads();

    // ---- Last block folds the 128 partials (deterministic order) ----
    if (s_last) {
        float s2 = (t < NBLK) ? g_psum[t] : 0.0f;
        int   c2 = (t < NBLK) ? g_pcnt[t] : 0;
        #pragma unroll
        for (int o = 16; o > 0; o >>= 1) {
            s2 += __shfl_xor_sync(0xffffffffu, s2, o);
            c2 += __shfl_xor_sync(0xffffffffu, c2, o);
        }
        if (lane == 0 && w < 4) { rsum[w] = s2; rcnt[w] = c2; }
        __syncthreads();
        if (t == 0) {
            float ts = rsum[0] + rsum[1] + rsum[2] + rsum[3];
            int   tc = rcnt[0] + rcnt[1] + rcnt[2] + rcnt[3];
            out[0] = (tc > 0) ? (ts / (float)tc) : 0.0f;
            g_flag = 0;   // reset for next graph replay
        }
    }
}

extern "C" void kernel_launch(void* const* d_in, const int* in_sizes, int n_in,
                              void* d_out, int out_size) {
    const float* e   = (const float*)d_in[0];
    const int*   lab = (const int*)d_in[1];
    k_fused<<<NBLK, NTHR>>>(e, lab, (float*)d_out);
}